// round 1
// baseline (speedup 1.0000x reference)
#include <cuda_runtime.h>
#include <math.h>

// ---------------- problem constants ----------------
#define kB   4
#define kS   1024
#define kD   1024
#define kH   16
#define kHD  64
#define kE   8
#define kDFF 4096
#define kNT  (kB * kS)     // 4096 tokens
#define MAXR (2 * kNT)     // 8192 gathered MoE rows (top-2 routing)

// ---------------- device scratch (no runtime alloc allowed) ----------------
__device__ float g_h[kNT * kD];
__device__ float g_q[kNT * kD];
__device__ float g_k[kNT * kD];
__device__ float g_v[kNT * kD];
__device__ float g_y[kNT * kD];
__device__ float g_att[(size_t)kB * kH * kS * kS];     // 256 MB
__device__ float g_hidden[(size_t)MAXR * kDFF];        // 128 MB
__device__ float g_cw[kNT * kE];
__device__ float g_hmean[kB * kD];
__device__ float g_cwseq[kB * kE];
__device__ int   g_cnt[kE];
__device__ int   g_off[kE];
__device__ int   g_cur[kE];
__device__ int   g_list[MAXR];

// ---------------- helpers ----------------
__device__ __forceinline__ float gelu_exact(float x) {
    return 0.5f * x * (1.0f + erff(x * 0.7071067811865476f));
}

__device__ __forceinline__ void top2_weights(const float* lg, int& i0, int& i1,
                                             float& w0, float& w1) {
    i0 = 0;
#pragma unroll
    for (int e = 1; e < kE; e++) if (lg[e] > lg[i0]) i0 = e;
    i1 = (i0 == 0) ? 1 : 0;
#pragma unroll
    for (int e = 0; e < kE; e++) if (e != i0 && lg[e] > lg[i1]) i1 = e;
    float ee = expf(lg[i1] - lg[i0]);   // <= 1
    w0 = 1.0f / (1.0f + ee);
    w1 = ee / (1.0f + ee);
}

// ---------------- layernorm ----------------
__global__ __launch_bounds__(256)
void ln_k(const float* __restrict__ x, const float* __restrict__ w,
          const float* __restrict__ b, float* __restrict__ out) {
    long row = blockIdx.x;
    const float* xr = x + row * kD;
    int tid = threadIdx.x;
    float4 xv = *(const float4*)(xr + tid * 4);
    float s  = xv.x + xv.y + xv.z + xv.w;
    float sq = xv.x * xv.x + xv.y * xv.y + xv.z * xv.z + xv.w * xv.w;
    __shared__ float rs[256], rq[256];
    rs[tid] = s; rq[tid] = sq;
    __syncthreads();
    for (int o = 128; o > 0; o >>= 1) {
        if (tid < o) { rs[tid] += rs[tid + o]; rq[tid] += rq[tid + o]; }
        __syncthreads();
    }
    float mean = rs[0] * (1.0f / kD);
    float var  = rq[0] * (1.0f / kD) - mean * mean;
    float rstd = rsqrtf(var + 1e-5f);
    float* orow = out + row * kD;
    int d = tid * 4;
    float4 wv = *(const float4*)(w + d);
    float4 bv = *(const float4*)(b + d);
    float4 ov;
    ov.x = (xv.x - mean) * rstd * wv.x + bv.x;
    ov.y = (xv.y - mean) * rstd * wv.y + bv.y;
    ov.z = (xv.z - mean) * rstd * wv.z + bv.z;
    ov.w = (xv.w - mean) * rstd * wv.w + bv.w;
    *(float4*)(orow + d) = ov;
}

// ---------------- causal softmax (in place over g_att rows) ----------------
__global__ __launch_bounds__(256)
void softmax_k(float* __restrict__ att) {
    int q = blockIdx.x;
    float* row = att + ((long)blockIdx.y * kS + q) * kS;
    int tid = threadIdx.x;
    __shared__ float sm[256];
    float m = -1e30f;
    for (int j = tid; j <= q; j += 256) m = fmaxf(m, row[j]);
    sm[tid] = m; __syncthreads();
    for (int o = 128; o > 0; o >>= 1) {
        if (tid < o) sm[tid] = fmaxf(sm[tid], sm[tid + o]);
        __syncthreads();
    }
    m = sm[0];
    __syncthreads();
    float s = 0.0f;
    for (int j = tid; j <= q; j += 256) {
        float e = expf(row[j] - m);
        row[j] = e;
        s += e;
    }
    sm[tid] = s; __syncthreads();
    for (int o = 128; o > 0; o >>= 1) {
        if (tid < o) sm[tid] += sm[tid + o];
        __syncthreads();
    }
    float inv = 1.0f / sm[0];
    for (int j = tid; j < kS; j += 256)
        row[j] = (j <= q) ? row[j] * inv : 0.0f;
}

// ---------------- gating ----------------
__global__ __launch_bounds__(128)
void gate_token_k(const float* __restrict__ h, const float* __restrict__ gw,
                  const float* __restrict__ gb, float* __restrict__ cw) {
    int t = blockIdx.x;
    int tid = threadIdx.x;
    float acc[kE];
#pragma unroll
    for (int e = 0; e < kE; e++) acc[e] = 0.0f;
    const float* hr = h + (long)t * kD;
    for (int d = tid; d < kD; d += 128) {
        float xv = hr[d];
        const float* g = gw + d * kE;
#pragma unroll
        for (int e = 0; e < kE; e++) acc[e] = fmaf(xv, g[e], acc[e]);
    }
    __shared__ float sm[kE][128];
#pragma unroll
    for (int e = 0; e < kE; e++) sm[e][tid] = acc[e];
    __syncthreads();
    for (int o = 64; o > 0; o >>= 1) {
        if (tid < o) {
#pragma unroll
            for (int e = 0; e < kE; e++) sm[e][tid] += sm[e][tid + o];
        }
        __syncthreads();
    }
    if (tid == 0) {
        float lg[kE];
#pragma unroll
        for (int e = 0; e < kE; e++) lg[e] = sm[e][0] + gb[e];
        int i0, i1; float w0, w1;
        top2_weights(lg, i0, i1, w0, w1);
#pragma unroll
        for (int e = 0; e < kE; e++) cw[t * kE + e] = 0.0f;
        cw[t * kE + i0] = w0;
        cw[t * kE + i1] = w1;
    }
}

__global__ void hmean_k(const float* __restrict__ h) {
    int idx = blockIdx.x * 256 + threadIdx.x;   // kB*kD = 4096 outputs
    int b = idx >> 10, d = idx & 1023;
    const float* p = h + (long)b * kS * kD + d;
    float s = 0.0f;
    for (int j = 0; j < kS; j++) s += p[(long)j * kD];
    g_hmean[idx] = s * (1.0f / kS);
}

__global__ void gate_seq_k(const float* __restrict__ gw, const float* __restrict__ gb) {
    int tid = threadIdx.x;              // 256 threads
    int pair = tid >> 3;                // (b,e) 0..31
    int part = tid & 7;
    int b = pair >> 3, e = pair & 7;
    float s = 0.0f;
    for (int d = part; d < kD; d += 8)
        s += g_hmean[b * kD + d] * gw[d * kE + e];
    __shared__ float sm[256];
    sm[tid] = s; __syncthreads();
    if (part == 0) {
        float tot = 0.0f;
#pragma unroll
        for (int i = 0; i < 8; i++) tot += sm[pair * 8 + i];
        sm[pair * 8] = tot + gb[e];
    }
    __syncthreads();
    if (tid < kB) {
        float lg[kE];
#pragma unroll
        for (int ee = 0; ee < kE; ee++) lg[ee] = sm[(tid * 8 + ee) * 8];
        int i0, i1; float w0, w1;
        top2_weights(lg, i0, i1, w0, w1);
#pragma unroll
        for (int ee = 0; ee < kE; ee++) g_cwseq[tid * kE + ee] = 0.0f;
        g_cwseq[tid * kE + i0] = w0;
        g_cwseq[tid * kE + i1] = w1;
    }
}

__global__ void bcast_cw_k(float* __restrict__ cw) {
    int i = blockIdx.x * 256 + threadIdx.x;  // kNT*kE = 32768
    int t = i >> 3, e = i & 7;
    cw[i] = g_cwseq[((t >> 10) << 3) + e];
}

// ---------------- routing gather ----------------
__global__ void zero_cnt_k() { if (threadIdx.x < kE) g_cnt[threadIdx.x] = 0; }

__global__ void count_k(const float* __restrict__ cw) {
    int t = blockIdx.x * 256 + threadIdx.x;
    if (t >= kNT) return;
#pragma unroll
    for (int e = 0; e < kE; e++)
        if (cw[t * kE + e] != 0.0f) atomicAdd(&g_cnt[e], 1);
}

__global__ void offsets_k() {
    if (threadIdx.x == 0) {
        int o = 0;
        for (int e = 0; e < kE; e++) { g_off[e] = o; g_cur[e] = o; o += g_cnt[e]; }
    }
}

__global__ void fill_k(const float* __restrict__ cw) {
    int t = blockIdx.x * 256 + threadIdx.x;
    if (t >= kNT) return;
#pragma unroll
    for (int e = 0; e < kE; e++)
        if (cw[t * kE + e] != 0.0f) {
            int p = atomicAdd(&g_cur[e], 1);
            g_list[p] = t;
        }
}

// ---------------- unified SGEMM ----------------
// MODE 0: C = A@W + bias                       (dense NN)
// MODE 1: C += A@W + bias                      (residual)
// MODE 2: C = 0.125 * A@B^T   batched bz=(b,h) (scores, causal tile-skip)
// MODE 3: C = A@W             batched bz=(b,h) (probs @ V, N=64, causal K-limit)
// MODE 4: hidden = gelu(gather(A)@W1[e]+b1[e]) (grid.z = expert)
// MODE 5: atomicAdd(x[tok], cw[tok,e]*(A@W2[e]+b2[e]))
struct GP {
    const float* A; const float* W; const float* bias; float* C;
    int M, N, K, lda, ldb, ldc;
    long strideW, strideBias;
};

#define BM 128
#define BN 128
#define BKK 8

template<int MODE>
__global__ __launch_bounds__(256)
void gemm_k(GP p) {
    const int bz = blockIdx.z;
    int M = p.M;
    const float* A = p.A;
    const float* W = p.W;
    const float* bias = p.bias;
    float* C = p.C;
    int rowbase = 0;

    if (MODE == 2) {
        long off = (long)(bz >> 4) * (kS * kD) + (long)(bz & 15) * kHD;
        A += off; W += off; C += (long)bz * kS * kS;
    } else if (MODE == 3) {
        long off = (long)(bz >> 4) * (kS * kD) + (long)(bz & 15) * kHD;
        A += (long)bz * kS * kS; W += off; C += off;
    } else if (MODE == 4 || MODE == 5) {
        M = g_cnt[bz];
        rowbase = g_off[bz];
        W += (long)bz * p.strideW;
        bias += (long)bz * p.strideBias;
    }

    int m0 = blockIdx.y * BM;
    int n0 = blockIdx.x * BN;
    if (m0 >= M) return;
    if (MODE == 2 && n0 > m0 + (BM - 1)) return;   // fully masked tile
    int Klim = p.K;
    if (MODE == 3) { int kl = m0 + BM; if (kl < Klim) Klim = kl; }

    __shared__ float As[BKK][BM];
    __shared__ float Bs[BKK][BN];

    int tid = threadIdx.x;
    // A tile load: 128 rows x 8 k, float4 along K
    int ar  = tid >> 1;
    int akc = (tid & 1) * 4;
    bool avalid = (m0 + ar) < M;
    const float* Ap;
    if (MODE == 4) {
        int tok = avalid ? g_list[rowbase + m0 + ar] : 0;
        Ap = A + (long)tok * p.lda + akc;
    } else if (MODE == 5) {
        Ap = A + (long)(rowbase + m0 + ar) * p.lda + akc;
    } else {
        Ap = A + (long)(m0 + ar) * p.lda + akc;
    }
    // B tile load
    const float* Wp;
    bool bvalid = true;
    int br = 0, bkc = 0, bk = 0, bnc = 0;
    if (MODE == 2) {           // B^T: rows are n, k along row
        br = tid >> 1; bkc = (tid & 1) * 4;
        Wp = W + (long)(n0 + br) * p.ldb + bkc;
    } else {
        bk = tid >> 5; bnc = (tid & 31) * 4;
        bvalid = (n0 + bnc) < p.N;
        Wp = W + (long)bk * p.ldb + n0 + bnc;
    }

    float acc[8][8];
#pragma unroll
    for (int i = 0; i < 8; i++)
#pragma unroll
        for (int j = 0; j < 8; j++) acc[i][j] = 0.0f;

    int ty = tid >> 4, tx = tid & 15;

    for (int kk = 0; kk < Klim; kk += BKK) {
        float4 a4 = avalid ? *(const float4*)Ap : make_float4(0, 0, 0, 0);
        As[akc + 0][ar] = a4.x; As[akc + 1][ar] = a4.y;
        As[akc + 2][ar] = a4.z; As[akc + 3][ar] = a4.w;
        Ap += BKK;
        if (MODE == 2) {
            float4 b4 = *(const float4*)Wp;
            Bs[bkc + 0][br] = b4.x; Bs[bkc + 1][br] = b4.y;
            Bs[bkc + 2][br] = b4.z; Bs[bkc + 3][br] = b4.w;
            Wp += BKK;
        } else {
            float4 b4 = bvalid ? *(const float4*)Wp : make_float4(0, 0, 0, 0);
            *(float4*)&Bs[bk][bnc] = b4;
            Wp += (long)BKK * p.ldb;
        }
        __syncthreads();
#pragma unroll
        for (int k = 0; k < BKK; k++) {
            float a[8], b[8];
            *(float4*)&a[0] = *(const float4*)&As[k][ty * 8];
            *(float4*)&a[4] = *(const float4*)&As[k][ty * 8 + 4];
            *(float4*)&b[0] = *(const float4*)&Bs[k][tx * 8];
            *(float4*)&b[4] = *(const float4*)&Bs[k][tx * 8 + 4];
#pragma unroll
            for (int i = 0; i < 8; i++)
#pragma unroll
                for (int j = 0; j < 8; j++)
                    acc[i][j] = fmaf(a[i], b[j], acc[i][j]);
        }
        __syncthreads();
    }

#pragma unroll
    for (int i = 0; i < 8; i++) {
        int m = m0 + ty * 8 + i;
        if (m >= M) continue;
        int tok = 0; float wgt = 0.0f;
        if (MODE == 5) {
            tok = g_list[rowbase + m];
            wgt = g_cw[tok * kE + bz];
        }
#pragma unroll
        for (int j = 0; j < 8; j++) {
            int n = n0 + tx * 8 + j;
            float v = acc[i][j];
            if (MODE == 0) {
                C[(long)m * p.ldc + n] = v + bias[n];
            } else if (MODE == 1) {
                C[(long)m * p.ldc + n] += v + bias[n];
            } else if (MODE == 2) {
                C[(long)m * p.ldc + n] = v * 0.125f;   // hd^-0.5
            } else if (MODE == 3) {
                if (n < p.N) C[(long)m * p.ldc + n] = v;
            } else if (MODE == 4) {
                C[(long)(rowbase + m) * p.ldc + n] = gelu_exact(v + bias[n]);
            } else {
                atomicAdd(&C[(long)tok * p.ldc + n], wgt * (v + bias[n]));
            }
        }
    }
}

// ---------------- host orchestration ----------------
extern "C" void kernel_launch(void* const* d_in, const int* in_sizes, int n_in,
                              void* d_out, int out_size) {
    const float* x_in = (const float*)d_in[0];
    const float* ln1w = (const float*)d_in[1];
    const float* ln1b = (const float*)d_in[2];
    const float* ln2w = (const float*)d_in[3];
    const float* ln2b = (const float*)d_in[4];
    const float* wq   = (const float*)d_in[5];
    const float* wk   = (const float*)d_in[6];
    const float* wv   = (const float*)d_in[7];
    const float* wo   = (const float*)d_in[8];
    const float* bq   = (const float*)d_in[9];
    const float* bk   = (const float*)d_in[10];
    const float* bv   = (const float*)d_in[11];
    const float* bo   = (const float*)d_in[12];
    const float* gw   = (const float*)d_in[13];
    const float* gb   = (const float*)d_in[14];
    const float* ew1  = (const float*)d_in[15];
    const float* eb1  = (const float*)d_in[16];
    const float* ew2  = (const float*)d_in[17];
    const float* eb2  = (const float*)d_in[18];
    float* xp = (float*)d_out;

    float *hp, *qp, *kp, *vp, *yp, *attp, *hidp, *cwp;
    cudaGetSymbolAddress((void**)&hp,   g_h);
    cudaGetSymbolAddress((void**)&qp,   g_q);
    cudaGetSymbolAddress((void**)&kp,   g_k);
    cudaGetSymbolAddress((void**)&vp,   g_v);
    cudaGetSymbolAddress((void**)&yp,   g_y);
    cudaGetSymbolAddress((void**)&attp, g_att);
    cudaGetSymbolAddress((void**)&hidp, g_hidden);
    cudaGetSymbolAddress((void**)&cwp,  g_cw);

    cudaMemcpyAsync(xp, x_in, (size_t)kNT * kD * sizeof(float),
                    cudaMemcpyDeviceToDevice);

    for (int l = 0; l < 2; l++) {
        // ---- attention block ----
        ln_k<<<kNT, 256>>>(xp, ln1w + l * kD, ln1b + l * kD, hp);

        GP p;
        p.A = hp; p.bias = bq + l * kD; p.C = qp;
        p.M = kNT; p.N = kD; p.K = kD; p.lda = kD; p.ldb = kD; p.ldc = kD;
        p.strideW = 0; p.strideBias = 0;
        p.W = wq + (long)l * kD * kD;
        gemm_k<0><<<dim3(kD / BN, kNT / BM, 1), 256>>>(p);
        p.W = wk + (long)l * kD * kD; p.bias = bk + l * kD; p.C = kp;
        gemm_k<0><<<dim3(kD / BN, kNT / BM, 1), 256>>>(p);
        p.W = wv + (long)l * kD * kD; p.bias = bv + l * kD; p.C = vp;
        gemm_k<0><<<dim3(kD / BN, kNT / BM, 1), 256>>>(p);

        GP ps; ps.A = qp; ps.W = kp; ps.bias = nullptr; ps.C = attp;
        ps.M = kS; ps.N = kS; ps.K = kHD; ps.lda = kD; ps.ldb = kD; ps.ldc = kS;
        ps.strideW = 0; ps.strideBias = 0;
        gemm_k<2><<<dim3(kS / BN, kS / BM, kB * kH), 256>>>(ps);

        softmax_k<<<dim3(kS, kB * kH), 256>>>(attp);

        GP pav; pav.A = attp; pav.W = vp; pav.bias = nullptr; pav.C = yp;
        pav.M = kS; pav.N = kHD; pav.K = kS; pav.lda = kS; pav.ldb = kD; pav.ldc = kD;
        pav.strideW = 0; pav.strideBias = 0;
        gemm_k<3><<<dim3(1, kS / BM, kB * kH), 256>>>(pav);

        GP po; po.A = yp; po.W = wo + (long)l * kD * kD;
        po.bias = bo + l * kD; po.C = xp;
        po.M = kNT; po.N = kD; po.K = kD; po.lda = kD; po.ldb = kD; po.ldc = kD;
        po.strideW = 0; po.strideBias = 0;
        gemm_k<1><<<dim3(kD / BN, kNT / BM, 1), 256>>>(po);

        // ---- MoE block ----
        ln_k<<<kNT, 256>>>(xp, ln2w + l * kD, ln2b + l * kD, hp);

        if (l % 2 == 0) {
            gate_token_k<<<kNT, 128>>>(hp, gw + (long)l * kD * kE, gb + l * kE, cwp);
        } else {
            hmean_k<<<kB * kD / 256, 256>>>(hp);
            gate_seq_k<<<1, 256>>>(gw + (long)l * kD * kE, gb + l * kE);
            bcast_cw_k<<<kNT * kE / 256, 256>>>(cwp);
        }

        zero_cnt_k<<<1, 32>>>();
        count_k<<<kNT / 256, 256>>>(cwp);
        offsets_k<<<1, 32>>>();
        fill_k<<<kNT / 256, 256>>>(cwp);

        GP p1; p1.A = hp; p1.W = ew1 + (long)l * kE * kD * kDFF;
        p1.bias = eb1 + (long)l * kE * kDFF; p1.C = hidp;
        p1.M = kNT; p1.N = kDFF; p1.K = kD;
        p1.lda = kD; p1.ldb = kDFF; p1.ldc = kDFF;
        p1.strideW = (long)kD * kDFF; p1.strideBias = kDFF;
        gemm_k<4><<<dim3(kDFF / BN, kNT / BM, kE), 256>>>(p1);

        GP p2; p2.A = hidp; p2.W = ew2 + (long)l * kE * kDFF * kD;
        p2.bias = eb2 + (long)l * kE * kD; p2.C = xp;
        p2.M = kNT; p2.N = kD; p2.K = kDFF;
        p2.lda = kDFF; p2.ldb = kD; p2.ldc = kD;
        p2.strideW = (long)kDFF * kD; p2.strideBias = kD;
        gemm_k<5><<<dim3(kD / BN, kNT / BM, kE), 256>>>(p2);
    }
}

// round 2
// speedup vs baseline: 2.5971x; 2.5971x over previous
#include <cuda_runtime.h>
#include <math.h>
#include <stdint.h>

// ---------------- problem constants ----------------
#define kB   4
#define kS   1024
#define kD   1024
#define kH   16
#define kHD  64
#define kE   8
#define kDFF 4096
#define kNT  (kB * kS)     // 4096 tokens
#define MAXR (2 * kNT)     // 8192 gathered MoE rows (top-2 routing)

// ---------------- device scratch (no runtime alloc allowed) ----------------
__device__ float g_h[kNT * kD];
__device__ float g_q[kNT * kD];
__device__ float g_k[kNT * kD];
__device__ float g_v[kNT * kD];
__device__ float g_y[kNT * kD];
__device__ float g_att[(size_t)kB * kH * kS * kS];     // 256 MB
__device__ float g_hidden[(size_t)MAXR * kDFF];        // 128 MB
__device__ float g_cw[kNT * kE];
__device__ float g_hmean[kB * kD];
__device__ float g_cwseq[kB * kE];
__device__ int   g_cnt[kE];
__device__ int   g_off[kE];
__device__ int   g_cur[kE];
__device__ int   g_list[MAXR];

// ---------------- helpers ----------------
__device__ __forceinline__ float gelu_exact(float x) {
    return 0.5f * x * (1.0f + erff(x * 0.7071067811865476f));
}

__device__ __forceinline__ void top2_weights(const float* lg, int& i0, int& i1,
                                             float& w0, float& w1) {
    i0 = 0;
#pragma unroll
    for (int e = 1; e < kE; e++) if (lg[e] > lg[i0]) i0 = e;
    i1 = (i0 == 0) ? 1 : 0;
#pragma unroll
    for (int e = 0; e < kE; e++) if (e != i0 && lg[e] > lg[i1]) i1 = e;
    float ee = expf(lg[i1] - lg[i0]);   // <= 1
    w0 = 1.0f / (1.0f + ee);
    w1 = ee / (1.0f + ee);
}

__device__ __forceinline__ void cp16(float* smem_dst, const float* gsrc, bool pred) {
    uint32_t s = (uint32_t)__cvta_generic_to_shared(smem_dst);
    int sz = pred ? 16 : 0;
    asm volatile("cp.async.cg.shared.global [%0], [%1], 16, %2;\n"
                 :: "r"(s), "l"(gsrc), "r"(sz));
}

__device__ __forceinline__ void mma_tf32(float* d, const uint32_t* a, const uint32_t* b) {
    asm volatile(
        "mma.sync.aligned.m16n8k8.row.col.f32.tf32.tf32.f32 "
        "{%0,%1,%2,%3}, {%4,%5,%6,%7}, {%8,%9}, {%0,%1,%2,%3};\n"
        : "+f"(d[0]), "+f"(d[1]), "+f"(d[2]), "+f"(d[3])
        : "r"(a[0]), "r"(a[1]), "r"(a[2]), "r"(a[3]),
          "r"(b[0]), "r"(b[1]));
}

// ---------------- layernorm ----------------
__global__ __launch_bounds__(256)
void ln_k(const float* __restrict__ x, const float* __restrict__ w,
          const float* __restrict__ b, float* __restrict__ out) {
    long row = blockIdx.x;
    const float* xr = x + row * kD;
    int tid = threadIdx.x;
    float4 xv = *(const float4*)(xr + tid * 4);
    float s  = xv.x + xv.y + xv.z + xv.w;
    float sq = xv.x * xv.x + xv.y * xv.y + xv.z * xv.z + xv.w * xv.w;
    __shared__ float rs[256], rq[256];
    rs[tid] = s; rq[tid] = sq;
    __syncthreads();
    for (int o = 128; o > 0; o >>= 1) {
        if (tid < o) { rs[tid] += rs[tid + o]; rq[tid] += rq[tid + o]; }
        __syncthreads();
    }
    float mean = rs[0] * (1.0f / kD);
    float var  = rq[0] * (1.0f / kD) - mean * mean;
    float rstd = rsqrtf(var + 1e-5f);
    float* orow = out + row * kD;
    int d = tid * 4;
    float4 wv = *(const float4*)(w + d);
    float4 bv = *(const float4*)(b + d);
    float4 ov;
    ov.x = (xv.x - mean) * rstd * wv.x + bv.x;
    ov.y = (xv.y - mean) * rstd * wv.y + bv.y;
    ov.z = (xv.z - mean) * rstd * wv.z + bv.z;
    ov.w = (xv.w - mean) * rstd * wv.w + bv.w;
    *(float4*)(orow + d) = ov;
}

// ---------------- causal softmax (in place over g_att rows) ----------------
__global__ __launch_bounds__(256)
void softmax_k(float* __restrict__ att) {
    int q = blockIdx.x;
    float* row = att + ((long)blockIdx.y * kS + q) * kS;
    int tid = threadIdx.x;
    __shared__ float sm[256];
    float m = -1e30f;
    for (int j = tid; j <= q; j += 256) m = fmaxf(m, row[j]);
    sm[tid] = m; __syncthreads();
    for (int o = 128; o > 0; o >>= 1) {
        if (tid < o) sm[tid] = fmaxf(sm[tid], sm[tid + o]);
        __syncthreads();
    }
    m = sm[0];
    __syncthreads();
    float s = 0.0f;
    for (int j = tid; j <= q; j += 256) {
        float e = expf(row[j] - m);
        row[j] = e;
        s += e;
    }
    sm[tid] = s; __syncthreads();
    for (int o = 128; o > 0; o >>= 1) {
        if (tid < o) sm[tid] += sm[tid + o];
        __syncthreads();
    }
    float inv = 1.0f / sm[0];
    for (int j = tid; j < kS; j += 256)
        row[j] = (j <= q) ? row[j] * inv : 0.0f;
}

// ---------------- gating ----------------
__global__ __launch_bounds__(128)
void gate_token_k(const float* __restrict__ h, const float* __restrict__ gw,
                  const float* __restrict__ gb, float* __restrict__ cw) {
    int t = blockIdx.x;
    int tid = threadIdx.x;
    float acc[kE];
#pragma unroll
    for (int e = 0; e < kE; e++) acc[e] = 0.0f;
    const float* hr = h + (long)t * kD;
    for (int d = tid; d < kD; d += 128) {
        float xv = hr[d];
        const float* g = gw + d * kE;
#pragma unroll
        for (int e = 0; e < kE; e++) acc[e] = fmaf(xv, g[e], acc[e]);
    }
    __shared__ float sm[kE][128];
#pragma unroll
    for (int e = 0; e < kE; e++) sm[e][tid] = acc[e];
    __syncthreads();
    for (int o = 64; o > 0; o >>= 1) {
        if (tid < o) {
#pragma unroll
            for (int e = 0; e < kE; e++) sm[e][tid] += sm[e][tid + o];
        }
        __syncthreads();
    }
    if (tid == 0) {
        float lg[kE];
#pragma unroll
        for (int e = 0; e < kE; e++) lg[e] = sm[e][0] + gb[e];
        int i0, i1; float w0, w1;
        top2_weights(lg, i0, i1, w0, w1);
#pragma unroll
        for (int e = 0; e < kE; e++) cw[t * kE + e] = 0.0f;
        cw[t * kE + i0] = w0;
        cw[t * kE + i1] = w1;
    }
}

__global__ void hmean_k(const float* __restrict__ h) {
    int idx = blockIdx.x * 256 + threadIdx.x;   // kB*kD = 4096 outputs
    int b = idx >> 10, d = idx & 1023;
    const float* p = h + (long)b * kS * kD + d;
    float s = 0.0f;
    for (int j = 0; j < kS; j++) s += p[(long)j * kD];
    g_hmean[idx] = s * (1.0f / kS);
}

__global__ void gate_seq_k(const float* __restrict__ gw, const float* __restrict__ gb) {
    int tid = threadIdx.x;              // 256 threads
    int pair = tid >> 3;                // (b,e) 0..31
    int part = tid & 7;
    int b = pair >> 3, e = pair & 7;
    float s = 0.0f;
    for (int d = part; d < kD; d += 8)
        s += g_hmean[b * kD + d] * gw[d * kE + e];
    __shared__ float sm[256];
    sm[tid] = s; __syncthreads();
    if (part == 0) {
        float tot = 0.0f;
#pragma unroll
        for (int i = 0; i < 8; i++) tot += sm[pair * 8 + i];
        sm[pair * 8] = tot + gb[e];
    }
    __syncthreads();
    if (tid < kB) {
        float lg[kE];
#pragma unroll
        for (int ee = 0; ee < kE; ee++) lg[ee] = sm[(tid * 8 + ee) * 8];
        int i0, i1; float w0, w1;
        top2_weights(lg, i0, i1, w0, w1);
#pragma unroll
        for (int ee = 0; ee < kE; ee++) g_cwseq[tid * kE + ee] = 0.0f;
        g_cwseq[tid * kE + i0] = w0;
        g_cwseq[tid * kE + i1] = w1;
    }
}

__global__ void bcast_cw_k(float* __restrict__ cw) {
    int i = blockIdx.x * 256 + threadIdx.x;  // kNT*kE = 32768
    int t = i >> 3, e = i & 7;
    cw[i] = g_cwseq[((t >> 10) << 3) + e];
}

// ---------------- routing gather ----------------
__global__ void zero_cnt_k() { if (threadIdx.x < kE) g_cnt[threadIdx.x] = 0; }

__global__ void count_k(const float* __restrict__ cw) {
    int t = blockIdx.x * 256 + threadIdx.x;
    if (t >= kNT) return;
#pragma unroll
    for (int e = 0; e < kE; e++)
        if (cw[t * kE + e] != 0.0f) atomicAdd(&g_cnt[e], 1);
}

__global__ void offsets_k() {
    if (threadIdx.x == 0) {
        int o = 0;
        for (int e = 0; e < kE; e++) { g_off[e] = o; g_cur[e] = o; o += g_cnt[e]; }
    }
}

__global__ void fill_k(const float* __restrict__ cw) {
    int t = blockIdx.x * 256 + threadIdx.x;
    if (t >= kNT) return;
#pragma unroll
    for (int e = 0; e < kE; e++)
        if (cw[t * kE + e] != 0.0f) {
            int p = atomicAdd(&g_cur[e], 1);
            g_list[p] = t;
        }
}

// ---------------- GEMM param struct ----------------
struct GP {
    const float* A; const float* W; const float* bias; float* C;
    int M, N, K, lda, ldb, ldc;
    long strideW, strideBias;
};

// ================= TF32 tensor-core GEMM =================
// MODE 0: C = A@W + bias            (dense NN)
// MODE 1: C += A@W + bias           (residual)
// MODE 4: hidden[rowbase+m] = gelu(A[g_list[m]]@W1[e] + b1[e])
// MODE 5: atomicAdd(C[tok], cw[tok,e]*(A[rowbase+m]@W2[e] + b2[e]))
// 128x128 CTA tile, BK=16, 8 warps (2x4), warp tile 64x32, 4-stage cp.async.
#define TSTAGES 4
#define TKTILE  16
#define TA_SZ   (128 * 20)           // A stage: 128 rows, stride 20 (pad 4)
#define TB_SZ   (16 * 136)           // B stage: 16 k-rows, stride 136 (pad 8)
#define TSTAGE_WORDS (TA_SZ + TB_SZ) // 4736
#define TSMEM_BYTES (TSTAGES * TSTAGE_WORDS * 4)  // 75776

template<int MODE>
__global__ __launch_bounds__(256)
void tgemm_k(GP p) {
    const int bz = blockIdx.z;
    int M = p.M;
    const float* A = p.A;
    const float* W = p.W;
    const float* bias = p.bias;
    float* C = p.C;
    int rowbase = 0;
    if (MODE == 4 || MODE == 5) {
        M = g_cnt[bz];
        rowbase = g_off[bz];
        W += (long)bz * p.strideW;
        bias += (long)bz * p.strideBias;
    }
    const int m0 = blockIdx.y * 128;
    const int n0 = blockIdx.x * 128;
    if (m0 >= M) return;

    extern __shared__ float smbuf[];
    const int tid = threadIdx.x;

    // ---- gmem load pointers (row-constant across K loop) ----
    const float* aptr[2]; bool avld[2]; int aoff[2];
#pragma unroll
    for (int i = 0; i < 2; i++) {
        int v  = tid + i * 256;
        int r  = v >> 2;            // 0..127
        int c4 = v & 3;             // float4 index along k
        int gr = m0 + r;
        avld[i] = gr < M;
        const float* ap;
        if (MODE == 4) {
            int tok = avld[i] ? g_list[rowbase + gr] : 0;
            ap = A + (long)tok * p.lda;
        } else if (MODE == 5) {
            ap = A + (long)(rowbase + (avld[i] ? gr : m0)) * p.lda;
        } else {
            ap = A + (long)(avld[i] ? gr : m0) * p.lda;
        }
        aptr[i] = ap + c4 * 4;
        aoff[i] = r * 20 + c4 * 4;
    }
    const float* bptr[2]; int boff[2];
#pragma unroll
    for (int i = 0; i < 2; i++) {
        int v  = tid + i * 256;
        int kr = v >> 5;            // 0..15
        int n4 = v & 31;            // float4 index along n
        bptr[i] = W + (long)kr * p.ldb + n0 + n4 * 4;
        boff[i] = TA_SZ + kr * 136 + n4 * 4;
    }

    const int NK = p.K / TKTILE;

    // prologue: fill first TSTAGES-1 stages
#pragma unroll
    for (int s = 0; s < TSTAGES - 1; s++) {
        if (s < NK) {
            float* st = smbuf + s * TSTAGE_WORDS;
#pragma unroll
            for (int i = 0; i < 2; i++)
                cp16(st + aoff[i], aptr[i] + s * TKTILE, avld[i]);
#pragma unroll
            for (int i = 0; i < 2; i++)
                cp16(st + boff[i], bptr[i] + (long)s * TKTILE * p.ldb, true);
        }
        asm volatile("cp.async.commit_group;\n" ::);
    }

    const int lane = tid & 31, wid = tid >> 5;
    const int wm = wid >> 2, wn = wid & 3;      // 2 x 4 warp grid
    const int g = lane >> 2, c = lane & 3;

    float acc[4][4][4];
#pragma unroll
    for (int a = 0; a < 4; a++)
#pragma unroll
        for (int b = 0; b < 4; b++)
#pragma unroll
            for (int d = 0; d < 4; d++) acc[a][b][d] = 0.0f;

    for (int kk = 0; kk < NK; kk++) {
        asm volatile("cp.async.wait_group %0;\n" :: "n"(TSTAGES - 2));
        __syncthreads();
        int lt = kk + TSTAGES - 1;
        if (lt < NK) {
            float* st = smbuf + (lt % TSTAGES) * TSTAGE_WORDS;
#pragma unroll
            for (int i = 0; i < 2; i++)
                cp16(st + aoff[i], aptr[i] + lt * TKTILE, avld[i]);
#pragma unroll
            for (int i = 0; i < 2; i++)
                cp16(st + boff[i], bptr[i] + (long)lt * TKTILE * p.ldb, true);
        }
        asm volatile("cp.async.commit_group;\n" ::);

        const float* As = smbuf + (kk % TSTAGES) * TSTAGE_WORDS;
        const float* Bs = As + TA_SZ;
#pragma unroll
        for (int k0 = 0; k0 < TKTILE; k0 += 8) {
            uint32_t af[4][4], bf[4][2];
#pragma unroll
            for (int mf = 0; mf < 4; mf++) {
                int base = (wm * 64 + mf * 16 + g) * 20 + k0 + c;
                af[mf][0] = __float_as_uint(As[base]);
                af[mf][1] = __float_as_uint(As[base + 160]);   // row +8
                af[mf][2] = __float_as_uint(As[base + 4]);     // col +4
                af[mf][3] = __float_as_uint(As[base + 164]);
            }
#pragma unroll
            for (int nf = 0; nf < 4; nf++) {
                int bb = (k0 + c) * 136 + wn * 32 + nf * 8 + g;
                bf[nf][0] = __float_as_uint(Bs[bb]);
                bf[nf][1] = __float_as_uint(Bs[bb + 544]);     // k +4
            }
#pragma unroll
            for (int mf = 0; mf < 4; mf++)
#pragma unroll
                for (int nf = 0; nf < 4; nf++)
                    mma_tf32(acc[mf][nf], af[mf], bf[nf]);
        }
    }

    // ---- epilogue ----
#pragma unroll
    for (int mf = 0; mf < 4; mf++) {
#pragma unroll
        for (int i2 = 0; i2 < 2; i2++) {
            int r = m0 + wm * 64 + mf * 16 + g + i2 * 8;
            if (r >= M) continue;
            int tok = 0; float wgt = 0.0f;
            if (MODE == 5) {
                tok = g_list[rowbase + r];
                wgt = g_cw[tok * kE + bz];
            }
#pragma unroll
            for (int nf = 0; nf < 4; nf++) {
                int nb = n0 + wn * 32 + nf * 8 + 2 * c;
                float v0 = acc[mf][nf][i2 * 2 + 0] + bias[nb];
                float v1 = acc[mf][nf][i2 * 2 + 1] + bias[nb + 1];
                if (MODE == 0) {
                    *(float2*)&C[(long)r * p.ldc + nb] = make_float2(v0, v1);
                } else if (MODE == 1) {
                    float2 old = *(float2*)&C[(long)r * p.ldc + nb];
                    *(float2*)&C[(long)r * p.ldc + nb] =
                        make_float2(old.x + v0, old.y + v1);
                } else if (MODE == 4) {
                    long rr = rowbase + r;
                    *(float2*)&C[rr * p.ldc + nb] =
                        make_float2(gelu_exact(v0), gelu_exact(v1));
                } else { // MODE 5
                    atomicAdd(&C[(long)tok * p.ldc + nb],     wgt * v0);
                    atomicAdd(&C[(long)tok * p.ldc + nb + 1], wgt * v1);
                }
            }
        }
    }
}

// ================= legacy fp32 SIMT GEMM (attention only) =================
// MODE 2: C = 0.125 * A@B^T   batched bz=(b,h) (scores, causal tile-skip)
// MODE 3: C = A@W             batched bz=(b,h) (probs @ V, N=64, causal K-limit)
#define BM 128
#define BN 128
#define BKK 8

template<int MODE>
__global__ __launch_bounds__(256)
void gemm_k(GP p) {
    const int bz = blockIdx.z;
    int M = p.M;
    const float* A = p.A;
    const float* W = p.W;
    float* C = p.C;

    if (MODE == 2) {
        long off = (long)(bz >> 4) * (kS * kD) + (long)(bz & 15) * kHD;
        A += off; W += off; C += (long)bz * kS * kS;
    } else if (MODE == 3) {
        long off = (long)(bz >> 4) * (kS * kD) + (long)(bz & 15) * kHD;
        A += (long)bz * kS * kS; W += off; C += off;
    }

    int m0 = blockIdx.y * BM;
    int n0 = blockIdx.x * BN;
    if (m0 >= M) return;
    if (MODE == 2 && n0 > m0 + (BM - 1)) return;   // fully masked tile
    int Klim = p.K;
    if (MODE == 3) { int kl = m0 + BM; if (kl < Klim) Klim = kl; }

    __shared__ float As[BKK][BM];
    __shared__ float Bs[BKK][BN];

    int tid = threadIdx.x;
    int ar  = tid >> 1;
    int akc = (tid & 1) * 4;
    bool avalid = (m0 + ar) < M;
    const float* Ap = A + (long)(m0 + ar) * p.lda + akc;

    const float* Wp;
    bool bvalid = true;
    int br = 0, bkc = 0, bk = 0, bnc = 0;
    if (MODE == 2) {           // B^T: rows are n, k along row
        br = tid >> 1; bkc = (tid & 1) * 4;
        Wp = W + (long)(n0 + br) * p.ldb + bkc;
    } else {
        bk = tid >> 5; bnc = (tid & 31) * 4;
        bvalid = (n0 + bnc) < p.N;
        Wp = W + (long)bk * p.ldb + n0 + bnc;
    }

    float acc[8][8];
#pragma unroll
    for (int i = 0; i < 8; i++)
#pragma unroll
        for (int j = 0; j < 8; j++) acc[i][j] = 0.0f;

    int ty = tid >> 4, tx = tid & 15;

    for (int kk = 0; kk < Klim; kk += BKK) {
        float4 a4 = avalid ? *(const float4*)Ap : make_float4(0, 0, 0, 0);
        As[akc + 0][ar] = a4.x; As[akc + 1][ar] = a4.y;
        As[akc + 2][ar] = a4.z; As[akc + 3][ar] = a4.w;
        Ap += BKK;
        if (MODE == 2) {
            float4 b4 = *(const float4*)Wp;
            Bs[bkc + 0][br] = b4.x; Bs[bkc + 1][br] = b4.y;
            Bs[bkc + 2][br] = b4.z; Bs[bkc + 3][br] = b4.w;
            Wp += BKK;
        } else {
            float4 b4 = bvalid ? *(const float4*)Wp : make_float4(0, 0, 0, 0);
            *(float4*)&Bs[bk][bnc] = b4;
            Wp += (long)BKK * p.ldb;
        }
        __syncthreads();
#pragma unroll
        for (int k = 0; k < BKK; k++) {
            float a[8], b[8];
            *(float4*)&a[0] = *(const float4*)&As[k][ty * 8];
            *(float4*)&a[4] = *(const float4*)&As[k][ty * 8 + 4];
            *(float4*)&b[0] = *(const float4*)&Bs[k][tx * 8];
            *(float4*)&b[4] = *(const float4*)&Bs[k][tx * 8 + 4];
#pragma unroll
            for (int i = 0; i < 8; i++)
#pragma unroll
                for (int j = 0; j < 8; j++)
                    acc[i][j] = fmaf(a[i], b[j], acc[i][j]);
        }
        __syncthreads();
    }

#pragma unroll
    for (int i = 0; i < 8; i++) {
        int m = m0 + ty * 8 + i;
        if (m >= M) continue;
#pragma unroll
        for (int j = 0; j < 8; j++) {
            int n = n0 + tx * 8 + j;
            float v = acc[i][j];
            if (MODE == 2) {
                C[(long)m * p.ldc + n] = v * 0.125f;   // hd^-0.5
            } else {
                if (n < p.N) C[(long)m * p.ldc + n] = v;
            }
        }
    }
}

// ---------------- host orchestration ----------------
extern "C" void kernel_launch(void* const* d_in, const int* in_sizes, int n_in,
                              void* d_out, int out_size) {
    const float* x_in = (const float*)d_in[0];
    const float* ln1w = (const float*)d_in[1];
    const float* ln1b = (const float*)d_in[2];
    const float* ln2w = (const float*)d_in[3];
    const float* ln2b = (const float*)d_in[4];
    const float* wq   = (const float*)d_in[5];
    const float* wk   = (const float*)d_in[6];
    const float* wv   = (const float*)d_in[7];
    const float* wo   = (const float*)d_in[8];
    const float* bq   = (const float*)d_in[9];
    const float* bk   = (const float*)d_in[10];
    const float* bv   = (const float*)d_in[11];
    const float* bo   = (const float*)d_in[12];
    const float* gw   = (const float*)d_in[13];
    const float* gb   = (const float*)d_in[14];
    const float* ew1  = (const float*)d_in[15];
    const float* eb1  = (const float*)d_in[16];
    const float* ew2  = (const float*)d_in[17];
    const float* eb2  = (const float*)d_in[18];
    float* xp = (float*)d_out;

    float *hp, *qp, *kp, *vp, *yp, *attp, *hidp, *cwp;
    cudaGetSymbolAddress((void**)&hp,   g_h);
    cudaGetSymbolAddress((void**)&qp,   g_q);
    cudaGetSymbolAddress((void**)&kp,   g_k);
    cudaGetSymbolAddress((void**)&vp,   g_v);
    cudaGetSymbolAddress((void**)&yp,   g_y);
    cudaGetSymbolAddress((void**)&attp, g_att);
    cudaGetSymbolAddress((void**)&hidp, g_hidden);
    cudaGetSymbolAddress((void**)&cwp,  g_cw);

    // opt-in to >48KB dynamic smem (idempotent, host-side, not captured)
    cudaFuncSetAttribute(tgemm_k<0>, cudaFuncAttributeMaxDynamicSharedMemorySize, TSMEM_BYTES);
    cudaFuncSetAttribute(tgemm_k<1>, cudaFuncAttributeMaxDynamicSharedMemorySize, TSMEM_BYTES);
    cudaFuncSetAttribute(tgemm_k<4>, cudaFuncAttributeMaxDynamicSharedMemorySize, TSMEM_BYTES);
    cudaFuncSetAttribute(tgemm_k<5>, cudaFuncAttributeMaxDynamicSharedMemorySize, TSMEM_BYTES);

    cudaMemcpyAsync(xp, x_in, (size_t)kNT * kD * sizeof(float),
                    cudaMemcpyDeviceToDevice);

    for (int l = 0; l < 2; l++) {
        // ---- attention block ----
        ln_k<<<kNT, 256>>>(xp, ln1w + l * kD, ln1b + l * kD, hp);

        GP p;
        p.A = hp; p.bias = bq + l * kD; p.C = qp;
        p.M = kNT; p.N = kD; p.K = kD; p.lda = kD; p.ldb = kD; p.ldc = kD;
        p.strideW = 0; p.strideBias = 0;
        p.W = wq + (long)l * kD * kD;
        tgemm_k<0><<<dim3(kD / 128, kNT / 128, 1), 256, TSMEM_BYTES>>>(p);
        p.W = wk + (long)l * kD * kD; p.bias = bk + l * kD; p.C = kp;
        tgemm_k<0><<<dim3(kD / 128, kNT / 128, 1), 256, TSMEM_BYTES>>>(p);
        p.W = wv + (long)l * kD * kD; p.bias = bv + l * kD; p.C = vp;
        tgemm_k<0><<<dim3(kD / 128, kNT / 128, 1), 256, TSMEM_BYTES>>>(p);

        GP ps; ps.A = qp; ps.W = kp; ps.bias = nullptr; ps.C = attp;
        ps.M = kS; ps.N = kS; ps.K = kHD; ps.lda = kD; ps.ldb = kD; ps.ldc = kS;
        ps.strideW = 0; ps.strideBias = 0;
        gemm_k<2><<<dim3(kS / BN, kS / BM, kB * kH), 256>>>(ps);

        softmax_k<<<dim3(kS, kB * kH), 256>>>(attp);

        GP pav; pav.A = attp; pav.W = vp; pav.bias = nullptr; pav.C = yp;
        pav.M = kS; pav.N = kHD; pav.K = kS; pav.lda = kS; pav.ldb = kD; pav.ldc = kD;
        pav.strideW = 0; pav.strideBias = 0;
        gemm_k<3><<<dim3(1, kS / BM, kB * kH), 256>>>(pav);

        GP po; po.A = yp; po.W = wo + (long)l * kD * kD;
        po.bias = bo + l * kD; po.C = xp;
        po.M = kNT; po.N = kD; po.K = kD; po.lda = kD; po.ldb = kD; po.ldc = kD;
        po.strideW = 0; po.strideBias = 0;
        tgemm_k<1><<<dim3(kD / 128, kNT / 128, 1), 256, TSMEM_BYTES>>>(po);

        // ---- MoE block ----
        ln_k<<<kNT, 256>>>(xp, ln2w + l * kD, ln2b + l * kD, hp);

        if (l % 2 == 0) {
            gate_token_k<<<kNT, 128>>>(hp, gw + (long)l * kD * kE, gb + l * kE, cwp);
        } else {
            hmean_k<<<kB * kD / 256, 256>>>(hp);
            gate_seq_k<<<1, 256>>>(gw + (long)l * kD * kE, gb + l * kE);
            bcast_cw_k<<<kNT * kE / 256, 256>>>(cwp);
        }

        zero_cnt_k<<<1, 32>>>();
        count_k<<<kNT / 256, 256>>>(cwp);
        offsets_k<<<1, 32>>>();
        fill_k<<<kNT / 256, 256>>>(cwp);

        GP p1; p1.A = hp; p1.W = ew1 + (long)l * kE * kD * kDFF;
        p1.bias = eb1 + (long)l * kE * kDFF; p1.C = hidp;
        p1.M = kNT; p1.N = kDFF; p1.K = kD;
        p1.lda = kD; p1.ldb = kDFF; p1.ldc = kDFF;
        p1.strideW = (long)kD * kDFF; p1.strideBias = kDFF;
        tgemm_k<4><<<dim3(kDFF / 128, kNT / 128, kE), 256, TSMEM_BYTES>>>(p1);

        GP p2; p2.A = hidp; p2.W = ew2 + (long)l * kE * kDFF * kD;
        p2.bias = eb2 + (long)l * kE * kD; p2.C = xp;
        p2.M = kNT; p2.N = kD; p2.K = kDFF;
        p2.lda = kDFF; p2.ldb = kD; p2.ldc = kD;
        p2.strideW = (long)kDFF * kD; p2.strideBias = kD;
        tgemm_k<5><<<dim3(kD / 128, kNT / 128, kE), 256, TSMEM_BYTES>>>(p2);
    }
}

// round 3
// speedup vs baseline: 3.6280x; 1.3970x over previous
#include <cuda_runtime.h>
#include <math.h>
#include <stdint.h>

// ---------------- problem constants ----------------
#define kB   4
#define kS   1024
#define kD   1024
#define kH   16
#define kHD  64
#define kE   8
#define kDFF 4096
#define kNT  (kB * kS)     // 4096 tokens
#define MAXR (2 * kNT)     // 8192 gathered MoE rows (top-2 routing)

// ---------------- device scratch (no runtime alloc allowed) ----------------
__device__ float g_h[kNT * kD];
__device__ float g_q[kNT * kD];
__device__ float g_k[kNT * kD];
__device__ float g_v[kNT * kD];
__device__ float g_y[kNT * kD];
__device__ float g_hidden[(size_t)MAXR * kDFF];        // 128 MB
__device__ float g_cw[kNT * kE];
__device__ float g_hmean[kB * kD];
__device__ float g_cwseq[kB * kE];
__device__ int   g_cnt[kE];
__device__ int   g_off[kE];
__device__ int   g_cur[kE];
__device__ int   g_list[MAXR];

// ---------------- helpers ----------------
__device__ __forceinline__ float gelu_exact(float x) {
    return 0.5f * x * (1.0f + erff(x * 0.7071067811865476f));
}

__device__ __forceinline__ uint32_t f2tf(float x) {   // round-to-nearest tf32
    uint32_t r;
    asm("cvt.rna.tf32.f32 %0, %1;" : "=r"(r) : "f"(x));
    return r;
}

__device__ __forceinline__ void top2_weights(const float* lg, int& i0, int& i1,
                                             float& w0, float& w1) {
    i0 = 0;
#pragma unroll
    for (int e = 1; e < kE; e++) if (lg[e] > lg[i0]) i0 = e;
    i1 = (i0 == 0) ? 1 : 0;
#pragma unroll
    for (int e = 0; e < kE; e++) if (e != i0 && lg[e] > lg[i1]) i1 = e;
    float ee = expf(lg[i1] - lg[i0]);   // <= 1
    w0 = 1.0f / (1.0f + ee);
    w1 = ee / (1.0f + ee);
}

__device__ __forceinline__ void cp16(float* smem_dst, const float* gsrc, bool pred) {
    uint32_t s = (uint32_t)__cvta_generic_to_shared(smem_dst);
    int sz = pred ? 16 : 0;
    asm volatile("cp.async.cg.shared.global [%0], [%1], 16, %2;\n"
                 :: "r"(s), "l"(gsrc), "r"(sz));
}

__device__ __forceinline__ void mma_tf32(float* d, const uint32_t* a, const uint32_t* b) {
    asm volatile(
        "mma.sync.aligned.m16n8k8.row.col.f32.tf32.tf32.f32 "
        "{%0,%1,%2,%3}, {%4,%5,%6,%7}, {%8,%9}, {%0,%1,%2,%3};\n"
        : "+f"(d[0]), "+f"(d[1]), "+f"(d[2]), "+f"(d[3])
        : "r"(a[0]), "r"(a[1]), "r"(a[2]), "r"(a[3]),
          "r"(b[0]), "r"(b[1]));
}

// ---------------- layernorm ----------------
__global__ __launch_bounds__(256)
void ln_k(const float* __restrict__ x, const float* __restrict__ w,
          const float* __restrict__ b, float* __restrict__ out) {
    long row = blockIdx.x;
    const float* xr = x + row * kD;
    int tid = threadIdx.x;
    float4 xv = *(const float4*)(xr + tid * 4);
    float s  = xv.x + xv.y + xv.z + xv.w;
    float sq = xv.x * xv.x + xv.y * xv.y + xv.z * xv.z + xv.w * xv.w;
    __shared__ float rs[256], rq[256];
    rs[tid] = s; rq[tid] = sq;
    __syncthreads();
    for (int o = 128; o > 0; o >>= 1) {
        if (tid < o) { rs[tid] += rs[tid + o]; rq[tid] += rq[tid + o]; }
        __syncthreads();
    }
    float mean = rs[0] * (1.0f / kD);
    float var  = rq[0] * (1.0f / kD) - mean * mean;
    float rstd = rsqrtf(var + 1e-5f);
    float* orow = out + row * kD;
    int d = tid * 4;
    float4 wv = *(const float4*)(w + d);
    float4 bv = *(const float4*)(b + d);
    float4 ov;
    ov.x = (xv.x - mean) * rstd * wv.x + bv.x;
    ov.y = (xv.y - mean) * rstd * wv.y + bv.y;
    ov.z = (xv.z - mean) * rstd * wv.z + bv.z;
    ov.w = (xv.w - mean) * rstd * wv.w + bv.w;
    *(float4*)(orow + d) = ov;
}

// ---------------- gating ----------------
__global__ __launch_bounds__(128)
void gate_token_k(const float* __restrict__ h, const float* __restrict__ gw,
                  const float* __restrict__ gb, float* __restrict__ cw) {
    int t = blockIdx.x;
    int tid = threadIdx.x;
    float acc[kE];
#pragma unroll
    for (int e = 0; e < kE; e++) acc[e] = 0.0f;
    const float* hr = h + (long)t * kD;
    for (int d = tid; d < kD; d += 128) {
        float xv = hr[d];
        const float* g = gw + d * kE;
#pragma unroll
        for (int e = 0; e < kE; e++) acc[e] = fmaf(xv, g[e], acc[e]);
    }
    __shared__ float sm[kE][128];
#pragma unroll
    for (int e = 0; e < kE; e++) sm[e][tid] = acc[e];
    __syncthreads();
    for (int o = 64; o > 0; o >>= 1) {
        if (tid < o) {
#pragma unroll
            for (int e = 0; e < kE; e++) sm[e][tid] += sm[e][tid + o];
        }
        __syncthreads();
    }
    if (tid == 0) {
        float lg[kE];
#pragma unroll
        for (int e = 0; e < kE; e++) lg[e] = sm[e][0] + gb[e];
        int i0, i1; float w0, w1;
        top2_weights(lg, i0, i1, w0, w1);
#pragma unroll
        for (int e = 0; e < kE; e++) cw[t * kE + e] = 0.0f;
        cw[t * kE + i0] = w0;
        cw[t * kE + i1] = w1;
    }
}

__global__ void hmean_k(const float* __restrict__ h) {
    int idx = blockIdx.x * 256 + threadIdx.x;   // kB*kD = 4096 outputs
    int b = idx >> 10, d = idx & 1023;
    const float* p = h + (long)b * kS * kD + d;
    float s = 0.0f;
    for (int j = 0; j < kS; j++) s += p[(long)j * kD];
    g_hmean[idx] = s * (1.0f / kS);
}

__global__ void gate_seq_k(const float* __restrict__ gw, const float* __restrict__ gb) {
    int tid = threadIdx.x;              // 256 threads
    int pair = tid >> 3;                // (b,e) 0..31
    int part = tid & 7;
    int b = pair >> 3, e = pair & 7;
    float s = 0.0f;
    for (int d = part; d < kD; d += 8)
        s += g_hmean[b * kD + d] * gw[d * kE + e];
    __shared__ float sm[256];
    sm[tid] = s; __syncthreads();
    if (part == 0) {
        float tot = 0.0f;
#pragma unroll
        for (int i = 0; i < 8; i++) tot += sm[pair * 8 + i];
        sm[pair * 8] = tot + gb[e];
    }
    __syncthreads();
    if (tid < kB) {
        float lg[kE];
#pragma unroll
        for (int ee = 0; ee < kE; ee++) lg[ee] = sm[(tid * 8 + ee) * 8];
        int i0, i1; float w0, w1;
        top2_weights(lg, i0, i1, w0, w1);
#pragma unroll
        for (int ee = 0; ee < kE; ee++) g_cwseq[tid * kE + ee] = 0.0f;
        g_cwseq[tid * kE + i0] = w0;
        g_cwseq[tid * kE + i1] = w1;
    }
}

__global__ void bcast_cw_k(float* __restrict__ cw) {
    int i = blockIdx.x * 256 + threadIdx.x;  // kNT*kE = 32768
    int t = i >> 3, e = i & 7;
    cw[i] = g_cwseq[((t >> 10) << 3) + e];
}

// ---------------- routing gather ----------------
__global__ void zero_cnt_k() { if (threadIdx.x < kE) g_cnt[threadIdx.x] = 0; }

__global__ void count_k(const float* __restrict__ cw) {
    int t = blockIdx.x * 256 + threadIdx.x;
    if (t >= kNT) return;
#pragma unroll
    for (int e = 0; e < kE; e++)
        if (cw[t * kE + e] != 0.0f) atomicAdd(&g_cnt[e], 1);
}

__global__ void offsets_k() {
    if (threadIdx.x == 0) {
        int o = 0;
        for (int e = 0; e < kE; e++) { g_off[e] = o; g_cur[e] = o; o += g_cnt[e]; }
    }
}

__global__ void fill_k(const float* __restrict__ cw) {
    int t = blockIdx.x * 256 + threadIdx.x;
    if (t >= kNT) return;
#pragma unroll
    for (int e = 0; e < kE; e++)
        if (cw[t * kE + e] != 0.0f) {
            int p = atomicAdd(&g_cur[e], 1);
            g_list[p] = t;
        }
}

// ---------------- GEMM param struct ----------------
struct GP {
    const float* A; const float* W; const float* bias; float* C;
    int M, N, K, lda, ldb, ldc;
    long strideW, strideBias;
};

// ================= TF32 tensor-core GEMM (CUTLASS-shaped) =================
// 128 threads (4 warps, 2x2), CTA tile 128x128, BK=32, warp tile 64x64,
// 3-stage cp.async pipeline, RNA tf32 rounding.
// MODE 0: C = A@W + bias
// MODE 1: C += A@W + bias            (residual)
// MODE 4: hidden[rowbase+m] = gelu(A[g_list[m]]@W1[e] + b1[e])
// MODE 5: atomicAdd(C[tok], cw[tok,e]*(A[rowbase+m]@W2[e] + b2[e]))
#define TSTAGES 3
#define TKTILE  32
#define TA_SZ   (128 * 36)            // A stage: [row][k], stride 36
#define TB_SZ   (32 * 136)            // B stage: [k][n],  stride 136
#define TSTAGE_WORDS (TA_SZ + TB_SZ)  // 8960
#define TSMEM_BYTES (TSTAGES * TSTAGE_WORDS * 4)  // 107520

template<int MODE>
__global__ __launch_bounds__(128)
void tgemm_k(GP p) {
    const int bz = blockIdx.z;
    int M = p.M;
    const float* A = p.A;
    const float* W = p.W;
    const float* bias = p.bias;
    float* C = p.C;
    int rowbase = 0;
    if (MODE == 4 || MODE == 5) {
        M = g_cnt[bz];
        rowbase = g_off[bz];
        W += (long)bz * p.strideW;
        bias += (long)bz * p.strideBias;
    }
    const int m0 = blockIdx.y * 128;
    const int n0 = blockIdx.x * 128;
    if (m0 >= M) return;

    extern __shared__ float smbuf[];
    const int tid = threadIdx.x;

    // ---- gmem load pointers: 8 A float4s + 8 B float4s per thread/stage ----
    const float* aptr[8]; bool avld[8]; int aoff[8];
#pragma unroll
    for (int j = 0; j < 8; j++) {
        int v  = tid + j * 128;
        int r  = v >> 3;            // 0..127
        int c4 = (v & 7) * 4;       // k position
        int gr = m0 + r;
        avld[j] = gr < M;
        const float* ap;
        if (MODE == 4) {
            int tok = avld[j] ? g_list[rowbase + gr] : 0;
            ap = A + (long)tok * p.lda;
        } else if (MODE == 5) {
            ap = A + (long)(rowbase + (avld[j] ? gr : m0)) * p.lda;
        } else {
            ap = A + (long)(avld[j] ? gr : m0) * p.lda;
        }
        aptr[j] = ap + c4;
        aoff[j] = r * 36 + c4;
    }
    const float* bptr[8]; int boff[8];
#pragma unroll
    for (int j = 0; j < 8; j++) {
        int v  = tid + j * 128;
        int kr = v >> 5;            // 0..31
        int n4 = (v & 31) * 4;      // n position
        bptr[j] = W + (long)kr * p.ldb + n0 + n4;
        boff[j] = TA_SZ + kr * 136 + n4;
    }

    const int NK = p.K / TKTILE;

    // prologue: fill first TSTAGES-1 stages
#pragma unroll
    for (int s = 0; s < TSTAGES - 1; s++) {
        if (s < NK) {
            float* st = smbuf + s * TSTAGE_WORDS;
#pragma unroll
            for (int j = 0; j < 8; j++)
                cp16(st + aoff[j], aptr[j] + s * TKTILE, avld[j]);
#pragma unroll
            for (int j = 0; j < 8; j++)
                cp16(st + boff[j], bptr[j] + (long)s * TKTILE * p.ldb, true);
        }
        asm volatile("cp.async.commit_group;\n" ::);
    }

    const int lane = tid & 31, wid = tid >> 5;
    const int wm = wid >> 1, wn = wid & 1;      // 2 x 2 warp grid, 64x64 tiles
    const int g = lane >> 2, c = lane & 3;

    float acc[4][8][4];
#pragma unroll
    for (int a = 0; a < 4; a++)
#pragma unroll
        for (int b = 0; b < 8; b++)
#pragma unroll
            for (int d = 0; d < 4; d++) acc[a][b][d] = 0.0f;

    for (int kk = 0; kk < NK; kk++) {
        asm volatile("cp.async.wait_group %0;\n" :: "n"(TSTAGES - 2));
        __syncthreads();
        int lt = kk + TSTAGES - 1;
        if (lt < NK) {
            float* st = smbuf + (lt % TSTAGES) * TSTAGE_WORDS;
#pragma unroll
            for (int j = 0; j < 8; j++)
                cp16(st + aoff[j], aptr[j] + lt * TKTILE, avld[j]);
#pragma unroll
            for (int j = 0; j < 8; j++)
                cp16(st + boff[j], bptr[j] + (long)lt * TKTILE * p.ldb, true);
        }
        asm volatile("cp.async.commit_group;\n" ::);

        const float* As = smbuf + (kk % TSTAGES) * TSTAGE_WORDS;
        const float* Bs = As + TA_SZ;
#pragma unroll
        for (int k0 = 0; k0 < TKTILE; k0 += 8) {
            uint32_t af[4][4], bf[8][2];
#pragma unroll
            for (int mf = 0; mf < 4; mf++) {
                int base = (wm * 64 + mf * 16 + g) * 36 + k0 + c;
                af[mf][0] = f2tf(As[base]);
                af[mf][1] = f2tf(As[base + 288]);   // row +8
                af[mf][2] = f2tf(As[base + 4]);     // k +4
                af[mf][3] = f2tf(As[base + 292]);
            }
#pragma unroll
            for (int nf = 0; nf < 8; nf++) {
                int bb = (k0 + c) * 136 + wn * 64 + nf * 8 + g;
                bf[nf][0] = f2tf(Bs[bb]);
                bf[nf][1] = f2tf(Bs[bb + 544]);     // k +4
            }
#pragma unroll
            for (int mf = 0; mf < 4; mf++)
#pragma unroll
                for (int nf = 0; nf < 8; nf++)
                    mma_tf32(acc[mf][nf], af[mf], bf[nf]);
        }
    }

    // ---- epilogue ----
#pragma unroll
    for (int mf = 0; mf < 4; mf++) {
#pragma unroll
        for (int i2 = 0; i2 < 2; i2++) {
            int r = m0 + wm * 64 + mf * 16 + g + i2 * 8;
            if (r >= M) continue;
            int tok = 0; float wgt = 0.0f;
            if (MODE == 5) {
                tok = g_list[rowbase + r];
                wgt = g_cw[tok * kE + bz];
            }
#pragma unroll
            for (int nf = 0; nf < 8; nf++) {
                int nb = n0 + wn * 64 + nf * 8 + 2 * c;
                float v0 = acc[mf][nf][i2 * 2 + 0] + bias[nb];
                float v1 = acc[mf][nf][i2 * 2 + 1] + bias[nb + 1];
                if (MODE == 0) {
                    *(float2*)&C[(long)r * p.ldc + nb] = make_float2(v0, v1);
                } else if (MODE == 1) {
                    float2 old = *(float2*)&C[(long)r * p.ldc + nb];
                    *(float2*)&C[(long)r * p.ldc + nb] =
                        make_float2(old.x + v0, old.y + v1);
                } else if (MODE == 4) {
                    long rr = rowbase + r;
                    *(float2*)&C[rr * p.ldc + nb] =
                        make_float2(gelu_exact(v0), gelu_exact(v1));
                } else { // MODE 5
                    atomicAdd(&C[(long)tok * p.ldc + nb],     wgt * v0);
                    atomicAdd(&C[(long)tok * p.ldc + nb + 1], wgt * v1);
                }
            }
        }
    }
}

// ================= fused flash attention (tf32 mma, fp32 softmax) =========
// grid (8 qtiles reversed, 64 batch-heads), 256 threads = 8 warps x 16 q-rows.
// smem: K tiles double-buffered [tok][d] stride 68, V tiles stride 72,
//       per-warp P buffer 16x132.
#define FA_KSTR 68
#define FA_VSTR 72
#define FA_PSTR 132
#define FA_KS_SZ (128 * FA_KSTR)
#define FA_VS_SZ (128 * FA_VSTR)
#define FA_PS_SZ (16 * FA_PSTR)
#define FA_SMEM_BYTES ((2 * FA_KS_SZ + 2 * FA_VS_SZ + 8 * FA_PS_SZ) * 4) // 210944

__global__ __launch_bounds__(256, 1)
void fattn_k(const float* __restrict__ qg, const float* __restrict__ kg,
             const float* __restrict__ vg, float* __restrict__ yg) {
    extern __shared__ float fs[];
    float* Ksm = fs;                                 // 2 stages
    float* Vsm = fs + 2 * FA_KS_SZ;                  // 2 stages
    float* Psm = fs + 2 * FA_KS_SZ + 2 * FA_VS_SZ;   // 8 warps

    const int bh = blockIdx.y;
    const int qt = (int)gridDim.x - 1 - (int)blockIdx.x;  // heavy tiles first
    const long base = (long)(bh >> 4) * ((long)kS * kD) + (long)(bh & 15) * kHD;
    const float* Q = qg + base;
    const float* K = kg + base;
    const float* V = vg + base;

    const int tid = threadIdx.x;
    const int lane = tid & 31, w = tid >> 5;
    const int g = lane >> 2, c = lane & 3;

    // Q fragments: rows qt*128 + w*16 + {g, g+8}, cols 0..63 (one-time load)
    uint32_t qa[8][4];
    {
        const float* q0 = Q + (long)(qt * 128 + w * 16 + g) * kD;
        const float* q8 = q0 + 8 * kD;
#pragma unroll
        for (int ks = 0; ks < 8; ks++) {
            qa[ks][0] = f2tf(q0[ks * 8 + c]);
            qa[ks][1] = f2tf(q8[ks * 8 + c]);
            qa[ks][2] = f2tf(q0[ks * 8 + c + 4]);
            qa[ks][3] = f2tf(q8[ks * 8 + c + 4]);
        }
    }

    float oacc[8][4];
#pragma unroll
    for (int nf = 0; nf < 8; nf++)
#pragma unroll
        for (int d = 0; d < 4; d++) oacc[nf][d] = 0.0f;
    float mrow0 = -1e30f, mrow1 = -1e30f, lrow0 = 0.0f, lrow1 = 0.0f;

    // K/V tile load: 128 rows x 64 floats each => 8 float4 per thread per tensor
    {
#pragma unroll
        for (int j = 0; j < 8; j++) {
            int v4 = tid + j * 256;
            int r = v4 >> 4, c4 = (v4 & 15) * 4;
            cp16(Ksm + r * FA_KSTR + c4, K + (long)r * kD + c4, true);
            cp16(Vsm + r * FA_VSTR + c4, V + (long)r * kD + c4, true);
        }
        asm volatile("cp.async.commit_group;\n" ::);
    }

    float* Pw = Psm + w * FA_PS_SZ;
    const int qr0 = w * 16 + g;          // local q row (within 128-tile)
    const int qr1 = qr0 + 8;

    for (int jt = 0; jt <= qt; jt++) {
        asm volatile("cp.async.wait_group 0;\n" ::);
        __syncthreads();
        if (jt < qt) {   // prefetch next K/V tile into other buffer
            int nb = (jt + 1) & 1;
            float* kd = Ksm + nb * FA_KS_SZ;
            float* vd = Vsm + nb * FA_VS_SZ;
#pragma unroll
            for (int j = 0; j < 8; j++) {
                int v4 = tid + j * 256;
                int r = v4 >> 4, c4 = (v4 & 15) * 4;
                cp16(kd + r * FA_KSTR + c4, K + (long)((jt + 1) * 128 + r) * kD + c4, true);
                cp16(vd + r * FA_VSTR + c4, V + (long)((jt + 1) * 128 + r) * kD + c4, true);
            }
        }
        asm volatile("cp.async.commit_group;\n" ::);

        const float* kd = Ksm + (jt & 1) * FA_KS_SZ;
        const float* vd = Vsm + (jt & 1) * FA_VS_SZ;

        // ---- S = Q @ K^T ----
        float sacc[16][4];
#pragma unroll
        for (int nf = 0; nf < 16; nf++)
#pragma unroll
            for (int d = 0; d < 4; d++) sacc[nf][d] = 0.0f;
#pragma unroll
        for (int ks = 0; ks < 8; ks++) {
#pragma unroll
            for (int nf = 0; nf < 16; nf++) {
                int bb = (nf * 8 + g) * FA_KSTR + ks * 8 + c;
                uint32_t bfr[2];
                bfr[0] = f2tf(kd[bb]);
                bfr[1] = f2tf(kd[bb + 4]);
                mma_tf32(sacc[nf], qa[ks], bfr);
            }
        }

        // ---- scale + causal mask + row max ----
        const bool diag = (jt == qt);
        float mx0 = -1e30f, mx1 = -1e30f;
#pragma unroll
        for (int nf = 0; nf < 16; nf++) {
            int kc = nf * 8 + 2 * c;
            float s0 = sacc[nf][0] * 0.125f;
            float s1 = sacc[nf][1] * 0.125f;
            float s2 = sacc[nf][2] * 0.125f;
            float s3 = sacc[nf][3] * 0.125f;
            if (diag) {
                if (kc     > qr0) s0 = -1e30f;
                if (kc + 1 > qr0) s1 = -1e30f;
                if (kc     > qr1) s2 = -1e30f;
                if (kc + 1 > qr1) s3 = -1e30f;
            }
            sacc[nf][0] = s0; sacc[nf][1] = s1;
            sacc[nf][2] = s2; sacc[nf][3] = s3;
            mx0 = fmaxf(mx0, fmaxf(s0, s1));
            mx1 = fmaxf(mx1, fmaxf(s2, s3));
        }
        mx0 = fmaxf(mx0, __shfl_xor_sync(0xffffffffu, mx0, 1));
        mx0 = fmaxf(mx0, __shfl_xor_sync(0xffffffffu, mx0, 2));
        mx1 = fmaxf(mx1, __shfl_xor_sync(0xffffffffu, mx1, 1));
        mx1 = fmaxf(mx1, __shfl_xor_sync(0xffffffffu, mx1, 2));

        float mnew0 = fmaxf(mrow0, mx0);
        float mnew1 = fmaxf(mrow1, mx1);
        float alpha0 = __expf(mrow0 - mnew0);
        float alpha1 = __expf(mrow1 - mnew1);

        // ---- exp, row sum, stage P in smem ----
        float rs0 = 0.0f, rs1 = 0.0f;
#pragma unroll
        for (int nf = 0; nf < 16; nf++) {
            float p0 = __expf(sacc[nf][0] - mnew0);
            float p1 = __expf(sacc[nf][1] - mnew0);
            float p2 = __expf(sacc[nf][2] - mnew1);
            float p3 = __expf(sacc[nf][3] - mnew1);
            rs0 += p0 + p1;
            rs1 += p2 + p3;
            int col = nf * 8 + 2 * c;
            *(float2*)&Pw[g * FA_PSTR + col]       = make_float2(p0, p1);
            *(float2*)&Pw[(g + 8) * FA_PSTR + col] = make_float2(p2, p3);
        }
        rs0 += __shfl_xor_sync(0xffffffffu, rs0, 1);
        rs0 += __shfl_xor_sync(0xffffffffu, rs0, 2);
        rs1 += __shfl_xor_sync(0xffffffffu, rs1, 1);
        rs1 += __shfl_xor_sync(0xffffffffu, rs1, 2);

        lrow0 = lrow0 * alpha0 + rs0;
        lrow1 = lrow1 * alpha1 + rs1;
        mrow0 = mnew0; mrow1 = mnew1;

#pragma unroll
        for (int nf = 0; nf < 8; nf++) {
            oacc[nf][0] *= alpha0; oacc[nf][1] *= alpha0;
            oacc[nf][2] *= alpha1; oacc[nf][3] *= alpha1;
        }
        __syncwarp();

        // ---- O += P @ V ----
#pragma unroll
        for (int k2 = 0; k2 < 16; k2++) {
            uint32_t pa[4];
            pa[0] = f2tf(Pw[g * FA_PSTR + k2 * 8 + c]);
            pa[1] = f2tf(Pw[(g + 8) * FA_PSTR + k2 * 8 + c]);
            pa[2] = f2tf(Pw[g * FA_PSTR + k2 * 8 + c + 4]);
            pa[3] = f2tf(Pw[(g + 8) * FA_PSTR + k2 * 8 + c + 4]);
#pragma unroll
            for (int nf = 0; nf < 8; nf++) {
                int bb = (k2 * 8 + c) * FA_VSTR + nf * 8 + g;
                uint32_t bfr[2];
                bfr[0] = f2tf(vd[bb]);
                bfr[1] = f2tf(vd[bb + 4 * FA_VSTR]);
                mma_tf32(oacc[nf], pa, bfr);
            }
        }
    }

    // ---- normalize + write out ----
    float inv0 = 1.0f / lrow0, inv1 = 1.0f / lrow1;
    float* y0 = yg + base + (long)(qt * 128 + w * 16 + g) * kD;
    float* y8 = y0 + 8 * kD;
#pragma unroll
    for (int nf = 0; nf < 8; nf++) {
        int col = nf * 8 + 2 * c;
        *(float2*)&y0[col] = make_float2(oacc[nf][0] * inv0, oacc[nf][1] * inv0);
        *(float2*)&y8[col] = make_float2(oacc[nf][2] * inv1, oacc[nf][3] * inv1);
    }
}

// ---------------- host orchestration ----------------
extern "C" void kernel_launch(void* const* d_in, const int* in_sizes, int n_in,
                              void* d_out, int out_size) {
    const float* x_in = (const float*)d_in[0];
    const float* ln1w = (const float*)d_in[1];
    const float* ln1b = (const float*)d_in[2];
    const float* ln2w = (const float*)d_in[3];
    const float* ln2b = (const float*)d_in[4];
    const float* wq   = (const float*)d_in[5];
    const float* wk   = (const float*)d_in[6];
    const float* wv   = (const float*)d_in[7];
    const float* wo   = (const float*)d_in[8];
    const float* bq   = (const float*)d_in[9];
    const float* bk   = (const float*)d_in[10];
    const float* bv   = (const float*)d_in[11];
    const float* bo   = (const float*)d_in[12];
    const float* gw   = (const float*)d_in[13];
    const float* gb   = (const float*)d_in[14];
    const float* ew1  = (const float*)d_in[15];
    const float* eb1  = (const float*)d_in[16];
    const float* ew2  = (const float*)d_in[17];
    const float* eb2  = (const float*)d_in[18];
    float* xp = (float*)d_out;

    float *hp, *qp, *kp, *vp, *yp, *hidp, *cwp;
    cudaGetSymbolAddress((void**)&hp,   g_h);
    cudaGetSymbolAddress((void**)&qp,   g_q);
    cudaGetSymbolAddress((void**)&kp,   g_k);
    cudaGetSymbolAddress((void**)&vp,   g_v);
    cudaGetSymbolAddress((void**)&yp,   g_y);
    cudaGetSymbolAddress((void**)&hidp, g_hidden);
    cudaGetSymbolAddress((void**)&cwp,  g_cw);

    cudaFuncSetAttribute(tgemm_k<0>, cudaFuncAttributeMaxDynamicSharedMemorySize, TSMEM_BYTES);
    cudaFuncSetAttribute(tgemm_k<1>, cudaFuncAttributeMaxDynamicSharedMemorySize, TSMEM_BYTES);
    cudaFuncSetAttribute(tgemm_k<4>, cudaFuncAttributeMaxDynamicSharedMemorySize, TSMEM_BYTES);
    cudaFuncSetAttribute(tgemm_k<5>, cudaFuncAttributeMaxDynamicSharedMemorySize, TSMEM_BYTES);
    cudaFuncSetAttribute(fattn_k, cudaFuncAttributeMaxDynamicSharedMemorySize, FA_SMEM_BYTES);

    cudaMemcpyAsync(xp, x_in, (size_t)kNT * kD * sizeof(float),
                    cudaMemcpyDeviceToDevice);

    for (int l = 0; l < 2; l++) {
        // ---- attention block ----
        ln_k<<<kNT, 256>>>(xp, ln1w + l * kD, ln1b + l * kD, hp);

        GP p;
        p.A = hp; p.bias = bq + l * kD; p.C = qp;
        p.M = kNT; p.N = kD; p.K = kD; p.lda = kD; p.ldb = kD; p.ldc = kD;
        p.strideW = 0; p.strideBias = 0;
        p.W = wq + (long)l * kD * kD;
        tgemm_k<0><<<dim3(kD / 128, kNT / 128, 1), 128, TSMEM_BYTES>>>(p);
        p.W = wk + (long)l * kD * kD; p.bias = bk + l * kD; p.C = kp;
        tgemm_k<0><<<dim3(kD / 128, kNT / 128, 1), 128, TSMEM_BYTES>>>(p);
        p.W = wv + (long)l * kD * kD; p.bias = bv + l * kD; p.C = vp;
        tgemm_k<0><<<dim3(kD / 128, kNT / 128, 1), 128, TSMEM_BYTES>>>(p);

        fattn_k<<<dim3(kS / 128, kB * kH), 256, FA_SMEM_BYTES>>>(qp, kp, vp, yp);

        GP po; po.A = yp; po.W = wo + (long)l * kD * kD;
        po.bias = bo + l * kD; po.C = xp;
        po.M = kNT; po.N = kD; po.K = kD; po.lda = kD; po.ldb = kD; po.ldc = kD;
        po.strideW = 0; po.strideBias = 0;
        tgemm_k<1><<<dim3(kD / 128, kNT / 128, 1), 128, TSMEM_BYTES>>>(po);

        // ---- MoE block ----
        ln_k<<<kNT, 256>>>(xp, ln2w + l * kD, ln2b + l * kD, hp);

        if (l % 2 == 0) {
            gate_token_k<<<kNT, 128>>>(hp, gw + (long)l * kD * kE, gb + l * kE, cwp);
        } else {
            hmean_k<<<kB * kD / 256, 256>>>(hp);
            gate_seq_k<<<1, 256>>>(gw + (long)l * kD * kE, gb + l * kE);
            bcast_cw_k<<<kNT * kE / 256, 256>>>(cwp);
        }

        zero_cnt_k<<<1, 32>>>();
        count_k<<<kNT / 256, 256>>>(cwp);
        offsets_k<<<1, 32>>>();
        fill_k<<<kNT / 256, 256>>>(cwp);

        GP p1; p1.A = hp; p1.W = ew1 + (long)l * kE * kD * kDFF;
        p1.bias = eb1 + (long)l * kE * kDFF; p1.C = hidp;
        p1.M = kNT; p1.N = kDFF; p1.K = kD;
        p1.lda = kD; p1.ldb = kDFF; p1.ldc = kDFF;
        p1.strideW = (long)kD * kDFF; p1.strideBias = kDFF;
        tgemm_k<4><<<dim3(kDFF / 128, kNT / 128, kE), 128, TSMEM_BYTES>>>(p1);

        GP p2; p2.A = hidp; p2.W = ew2 + (long)l * kE * kDFF * kD;
        p2.bias = eb2 + (long)l * kE * kD; p2.C = xp;
        p2.M = kNT; p2.N = kD; p2.K = kDFF;
        p2.lda = kDFF; p2.ldb = kD; p2.ldc = kD;
        p2.strideW = (long)kDFF * kD; p2.strideBias = kD;
        tgemm_k<5><<<dim3(kD / 128, kNT / 128, kE), 128, TSMEM_BYTES>>>(p2);
    }
}